// round 14
// baseline (speedup 1.0000x reference)
#include <cuda_runtime.h>
#include <cuda_bf16.h>
#include <math.h>
#include <stdint.h>

// ---------------- problem constants ----------------
#define NB 512          // batch
#define ND 512          // embed dim
#define MAX_C 100000
#define CTILE 64        // classes per CTA (M)
#define STILE 256       // samples per CTA (N), grid.y covers B
#define KCH 64          // K chunk (2-stage pipeline)
#define NCHK (ND / KCH) // 8
#define NCBLK_MAX ((MAX_C + CTILE - 1) / CTILE)   // 1563
#define WPAD (NCBLK_MAX * CTILE)                  // 100032 (padded rows)
#define NPART_MAX (NCBLK_MAX * 2)                 // 2 partials per CTA (per warp_m)

// ArcFace constants (margin=0.5, scale=64, t=0.2)
#define ARC_COS_M 0.8775825618903728f
#define ARC_SIN_M 0.479425538604203f
#define ARC_TH   (-0.8775825618903728f)
#define ARC_MM    0.2397127693021015f
#define ARC_EPS   1e-7f
#define ARC_SCALE 64.0f
#define FIX_MAX   90.0f   // > 64*(1.2*1+0.2) = 89.6, absolute logit bound

// ---------------- static scratch ----------------
__device__ float          g_en [NB * ND];         // normalized embeddings fp32
__device__ __nv_bfloat16  g_ebf[NB * ND];         // normalized embeddings bf16
__device__ __nv_bfloat16  g_wbf[(size_t)WPAD * ND]; // normalized weights bf16 (padded)
__device__ float          g_phi[NB];
__device__ int            g_gt [NB];
__device__ float          g_part[(size_t)NB * NPART_MAX];  // sum of exp(v-90)
__device__ float          g_samp[NB];
__device__ int            g_gt_is_i32;

// ---------------- PTX helpers (plain-sm_103-safe) ----------------
__device__ __forceinline__ uint32_t s2u(const void* p) {
    uint32_t a;
    asm("{ .reg .u64 t; cvta.to.shared.u64 t, %1; cvt.u32.u64 %0, t; }" : "=r"(a) : "l"(p));
    return a;
}
#define LDSM_X4(r0, r1, r2, r3, addr)                                          \
    asm volatile("ldmatrix.sync.aligned.m8n8.x4.shared.b16 {%0,%1,%2,%3}, [%4];" \
                 : "=r"(r0), "=r"(r1), "=r"(r2), "=r"(r3) : "r"(addr))
__device__ __forceinline__ void mma16816(float* c, const uint32_t* a, const uint32_t* b) {
    asm volatile(
        "mma.sync.aligned.m16n8k16.row.col.f32.bf16.bf16.f32 "
        "{%0,%1,%2,%3}, {%4,%5,%6,%7}, {%8,%9}, {%0,%1,%2,%3};"
        : "+f"(c[0]), "+f"(c[1]), "+f"(c[2]), "+f"(c[3])
        : "r"(a[0]), "r"(a[1]), "r"(a[2]), "r"(a[3]), "r"(b[0]), "r"(b[1]));
}
#define CP_ASYNC16(dst, src)                                                   \
    asm volatile("cp.async.cg.shared.global [%0], [%1], 16;"                   \
                 :: "r"(dst), "l"(src) : "memory")
#define CP_COMMIT()  asm volatile("cp.async.commit_group;" ::: "memory")
#define CP_WAIT(n)   asm volatile("cp.async.wait_group %0;" :: "n"(n) : "memory")

// ---------------- K0: probe gt dtype (int64 vs int32) ----------------
__global__ void k_probe(const void* __restrict__ gt, int B, int C) {
    const long long* p = (const long long*)gt;
    int t = threadIdx.x;
    int bad = 0;
    for (int i = t; i < B; i += 256) {
        long long v = p[i];
        if (v < 0 || v >= (long long)C) bad = 1;
    }
    __shared__ int sh[256];
    sh[t] = bad; __syncthreads();
    for (int o = 128; o > 0; o >>= 1) { if (t < o) sh[t] |= sh[t + o]; __syncthreads(); }
    if (t == 0) g_gt_is_i32 = sh[0];
}

// ---------------- K1: normalize embedding rows (fp32 + bf16 copies) ----------------
__global__ void k_norm_e(const float* __restrict__ e) {
    int b = blockIdx.x, t = threadIdx.x;
    float ss = 0.f;
    for (int d = t; d < ND; d += 256) { float v = e[(size_t)b * ND + d]; ss += v * v; }
    __shared__ float sh[256];
    sh[t] = ss; __syncthreads();
    for (int o = 128; o > 0; o >>= 1) { if (t < o) sh[t] += sh[t + o]; __syncthreads(); }
    float rn = rsqrtf(sh[0]);
    for (int d = t; d < ND; d += 256) {
        float v = e[(size_t)b * ND + d] * rn;
        g_en [(size_t)b * ND + d] = v;
        g_ebf[(size_t)b * ND + d] = __float2bfloat16(v);
    }
}

// ---------------- K2: W fp32 -> normalized bf16 (one warp per row) ----------------
__global__ void k_wconv(const float* __restrict__ w, int C) {
    int row  = blockIdx.x * 8 + (threadIdx.x >> 5);
    int lane = threadIdx.x & 31;
    __nv_bfloat16* dst = g_wbf + (size_t)row * ND;
    if (row >= C) {                       // zero-pad rows beyond C
        uint2 z = make_uint2(0u, 0u);
        #pragma unroll
        for (int i = 0; i < 4; i++)
            *(uint2*)(dst + (lane + 32 * i) * 4) = z;
        return;
    }
    const float* src = w + (size_t)row * ND;
    float4 v[4];
    float ssq = 0.f;
    #pragma unroll
    for (int i = 0; i < 4; i++) {
        v[i] = *(const float4*)(src + (lane + 32 * i) * 4);
        ssq += v[i].x * v[i].x + v[i].y * v[i].y + v[i].z * v[i].z + v[i].w * v[i].w;
    }
    #pragma unroll
    for (int o = 16; o > 0; o >>= 1)
        ssq += __shfl_xor_sync(0xffffffffu, ssq, o);
    float rn = rsqrtf(ssq);
    #pragma unroll
    for (int i = 0; i < 4; i++) {
        __nv_bfloat162 lo = __float22bfloat162_rn(make_float2(v[i].x * rn, v[i].y * rn));
        __nv_bfloat162 hi = __float22bfloat162_rn(make_float2(v[i].z * rn, v[i].w * rn));
        uint2 pk;
        pk.x = *(uint32_t*)&lo;
        pk.y = *(uint32_t*)&hi;
        *(uint2*)(dst + (lane + 32 * i) * 4) = pk;
    }
}

// ---------------- K3: per-sample pos/phi (fp32 exact) ----------------
__global__ void k_phi(const float* __restrict__ w, const void* __restrict__ gt, int C) {
    int b = blockIdx.x, t = threadIdx.x;
    __shared__ int sg;
    if (t == 0) {
        long long v;
        if (g_gt_is_i32) v = (long long)((const int*)gt)[b];
        else             v = ((const long long*)gt)[b];
        if (v < 0) v = 0;
        if (v >= C) v = C - 1;
        sg = (int)v;
    }
    __syncthreads();
    int g = sg;
    const float* er = g_en + (size_t)b * ND;
    const float* wr = w + (size_t)g * ND;
    float s = 0.f, q = 0.f;
    for (int d = t; d < ND; d += 256) { float wv = wr[d]; s += er[d] * wv; q += wv * wv; }
    __shared__ float shs[256], shq[256];
    shs[t] = s; shq[t] = q; __syncthreads();
    for (int o = 128; o > 0; o >>= 1) {
        if (t < o) { shs[t] += shs[t + o]; shq[t] += shq[t + o]; }
        __syncthreads();
    }
    if (t == 0) {
        float pos = shs[0] * rsqrtf(shq[0]);
        pos = fminf(fmaxf(pos, -1.f + ARC_EPS), 1.f - ARC_EPS);
        float s2 = fminf(fmaxf(1.f - pos * pos, ARC_EPS), 1.f - ARC_EPS);
        float ph = pos * ARC_COS_M - sqrtf(s2) * ARC_SIN_M;
        if (!(pos > ARC_TH)) ph = pos - ARC_MM;
        g_phi[b] = ph;
        g_gt[b] = g;
    }
}

// ---------------- K4: HMMA GEMM + margin + partial sum-exp ----------------
// 256 threads, 8 warps: warp_m(2) x warp_n(4); warp tile 32 cls x 64 smp.
// CTA tile 64 cls x 256 smp; BOTH operands streamed (bf16) via cp.async,
// 2-stage pipeline; ~84KB smem + 128 regs -> 2 CTAs/SM (independent streams).
#define W_BUF (CTILE * KCH * 2)                // 8192
#define E_BUF (STILE * KCH * 2)                // 32768
#define SM_E0 (2 * W_BUF)                      // 16384
#define SM_PHI (SM_E0 + 2 * E_BUF)             // 81920
#define SM_GT  (SM_PHI + STILE * 4)            // 82944
#define SMEM_NEED (SM_GT + STILE * 4 + 128)    // 84096

__global__ __launch_bounds__(256, 2) void k_gemm(int C, int npart) {
    extern __shared__ char smp[];
    const uint32_t sb = s2u(smp);
    float* phi_sm = (float*)(smp + SM_PHI);
    int*   gt_sm  = (int*)  (smp + SM_GT);

    const int t    = threadIdx.x;
    const int wid  = t >> 5;
    const int lane = t & 31;
    const int warp_m = wid >> 2;   // 0..1 : 32 classes each
    const int warp_n = wid & 3;    // 0..3 : 64 samples each
    const int cn0 = blockIdx.x * CTILE;
    const int s0  = blockIdx.y * STILE;

    // loader mapping (256 threads):
    //   W tile 64 rows x 128B: 4 threads/row, 2 x 16B units each
    //   E tile 256 rows x 128B: 1 thread/row, 8 x 16B units each
    const int wRow  = t >> 2;
    const int wCol0 = (t & 3) * 2;
    const int eRow  = t;

#define ISSUE_CHUNK(kh, buf) do {                                                \
    { unsigned long long _ws = __cvta_generic_to_global(                        \
          g_wbf + (size_t)(cn0 + wRow) * ND + (kh) * KCH + wCol0 * 8);           \
      uint32_t _wd = sb + (uint32_t)((buf) * W_BUF) + (uint32_t)wRow * 128u;     \
      uint32_t _sz = (uint32_t)((wRow & 7) << 4);                                \
      CP_ASYNC16(_wd + (((uint32_t)((wCol0 + 0) * 16)) ^ _sz), _ws);             \
      CP_ASYNC16(_wd + (((uint32_t)((wCol0 + 1) * 16)) ^ _sz), _ws + 16); }      \
    { unsigned long long _es = __cvta_generic_to_global(                         \
          g_ebf + (size_t)(s0 + eRow) * ND + (kh) * KCH);                        \
      uint32_t _ed = sb + (uint32_t)(SM_E0 + (buf) * E_BUF) + (uint32_t)eRow * 128u; \
      uint32_t _sz = (uint32_t)((eRow & 7) << 4);                                \
      CP_ASYNC16(_ed + (((uint32_t)(0 * 16)) ^ _sz), _es);                       \
      CP_ASYNC16(_ed + (((uint32_t)(1 * 16)) ^ _sz), _es + 16);                  \
      CP_ASYNC16(_ed + (((uint32_t)(2 * 16)) ^ _sz), _es + 32);                  \
      CP_ASYNC16(_ed + (((uint32_t)(3 * 16)) ^ _sz), _es + 48);                  \
      CP_ASYNC16(_ed + (((uint32_t)(4 * 16)) ^ _sz), _es + 64);                  \
      CP_ASYNC16(_ed + (((uint32_t)(5 * 16)) ^ _sz), _es + 80);                  \
      CP_ASYNC16(_ed + (((uint32_t)(6 * 16)) ^ _sz), _es + 96);                  \
      CP_ASYNC16(_ed + (((uint32_t)(7 * 16)) ^ _sz), _es + 112); }               \
    CP_COMMIT();                                                                 \
} while (0)

    // kick off pipeline
    ISSUE_CHUNK(0, 0);
    ISSUE_CHUNK(1, 1);

    // phi/gt for this CTA's samples
    phi_sm[t] = g_phi[s0 + t];
    gt_sm[t]  = g_gt[s0 + t];

    // ---- per-lane ldmatrix address components (loop-invariant) ----
    const uint32_t swzx  = (uint32_t)((lane & 7) << 4);
    const uint32_t aOff0 = (uint32_t)((warp_m * 32 + (lane & 15)) * 128);
    const uint32_t aOff1 = aOff0 + 16u * 128u;
    const uint32_t kOffA = (uint32_t)((lane >> 4) << 3);
    const uint32_t bRowLoc = (uint32_t)(((lane >> 4) << 3) + (lane & 7));
    const uint32_t bOffBase = (uint32_t)((warp_n * 64 + bRowLoc) * 128);
    const uint32_t kOffB = (uint32_t)(((lane >> 3) & 1) << 3);

    float acc[2][8][4];
    #pragma unroll
    for (int mi = 0; mi < 2; mi++)
        #pragma unroll
        for (int ni = 0; ni < 8; ni++)
            #pragma unroll
            for (int q = 0; q < 4; q++) acc[mi][ni][q] = 0.f;

    #pragma unroll
    for (int kh = 0; kh < NCHK; kh++) {
        const int buf = kh & 1;
        if (kh + 1 < NCHK) { CP_WAIT(1); } else { CP_WAIT(0); }
        __syncthreads();                 // chunk kh visible to all warps

        const uint32_t aBuf = sb + (uint32_t)(buf * W_BUF);
        const uint32_t bBuf = sb + (uint32_t)(SM_E0 + buf * E_BUF);
        #pragma unroll
        for (int k0 = 0; k0 < KCH; k0 += 16) {
            uint32_t offA = (((uint32_t)k0 + kOffA) << 1) ^ swzx;
            uint32_t offB = (((uint32_t)k0 + kOffB) << 1) ^ swzx;
            uint32_t a0[4], a1[4], b[8][2];
            LDSM_X4(a0[0], a0[1], a0[2], a0[3], aBuf + aOff0 + offA);
            LDSM_X4(a1[0], a1[1], a1[2], a1[3], aBuf + aOff1 + offA);
            LDSM_X4(b[0][0], b[0][1], b[1][0], b[1][1], bBuf + bOffBase + offB);
            LDSM_X4(b[2][0], b[2][1], b[3][0], b[3][1], bBuf + bOffBase + 16u * 128u + offB);
            LDSM_X4(b[4][0], b[4][1], b[5][0], b[5][1], bBuf + bOffBase + 32u * 128u + offB);
            LDSM_X4(b[6][0], b[6][1], b[7][0], b[7][1], bBuf + bOffBase + 48u * 128u + offB);
            #pragma unroll
            for (int ni = 0; ni < 8; ni++) {
                mma16816(acc[0][ni], a0, b[ni]);
                mma16816(acc[1][ni], a1, b[ni]);
            }
        }
        __syncthreads();                 // buffer consumed, safe to refill
        if (kh + 2 < NCHK) ISSUE_CHUNK(kh + 2, buf);
    }

    // ---- epilogue: margin transform + fixed-max sum-exp ----
    // acc[mi][ni][rh*2+i]: class = warp_m*32 + mi*16 + (lane>>2) + rh*8
    //                      sample = warp_n*64 + ni*8 + 2*(lane&3) + i
    const float HI = 1.f - ARC_EPS, LO = -1.f + ARC_EPS;
    #pragma unroll
    for (int ni = 0; ni < 8; ni++) {
        #pragma unroll
        for (int i = 0; i < 2; i++) {
            const int sLoc = warp_n * 64 + ni * 8 + 2 * (lane & 3) + i;
            const float ph = phi_sm[sLoc];
            const int   gi = gt_sm[sLoc];
            float sum = 0.f;
            #pragma unroll
            for (int mi = 0; mi < 2; mi++) {
                #pragma unroll
                for (int rh = 0; rh < 2; rh++) {
                    const int clsLoc = warp_m * 32 + mi * 16 + (lane >> 2) + rh * 8;
                    const int c = cn0 + clsLoc;
                    if (c < C) {
                        float cv = acc[mi][ni][rh * 2 + i];
                        cv = fminf(fmaxf(cv, LO), HI);
                        float v = (cv > ph) ? fmaf(1.2f, cv, 0.2f) : cv;
                        if (c == gi) v = ph;
                        sum += __expf(fmaf(v, ARC_SCALE, -FIX_MAX));
                    }
                }
            }
            // reduce across the 8 lanes holding this sample (lane>>2 = 0..7)
            sum += __shfl_xor_sync(0xffffffffu, sum, 4);
            sum += __shfl_xor_sync(0xffffffffu, sum, 8);
            sum += __shfl_xor_sync(0xffffffffu, sum, 16);
            if ((lane >> 2) == 0)
                g_part[(size_t)(s0 + sLoc) * npart + blockIdx.x * 2 + warp_m] = sum;
        }
    }
#undef ISSUE_CHUNK
}

// ---------------- K5: per-sample combine (plain sum, fixed max) ----------------
__global__ void k_lse(int npart) {
    int b = blockIdx.x, t = threadIdx.x;
    const float* p = g_part + (size_t)b * npart;
    float s = 0.f;
    for (int i = t; i < npart; i += 256) s += p[i];
    __shared__ float sh[256];
    sh[t] = s; __syncthreads();
    for (int o = 128; o > 0; o >>= 1) { if (t < o) sh[t] += sh[t + o]; __syncthreads(); }
    if (t == 0) g_samp[b] = FIX_MAX + logf(sh[0]) - ARC_SCALE * g_phi[b];
}

// ---------------- K6: mean -> loss ----------------
__global__ void k_loss(float* __restrict__ out, int B) {
    int t = threadIdx.x;
    float s = 0.f;
    for (int i = t; i < B; i += 256) s += g_samp[i];
    __shared__ float sh[256];
    sh[t] = s; __syncthreads();
    for (int o = 128; o > 0; o >>= 1) { if (t < o) sh[t] += sh[t + o]; __syncthreads(); }
    if (t == 0) out[0] = sh[0] / (float)B;
}

// ---------------- launch ----------------
extern "C" void kernel_launch(void* const* d_in, const int* in_sizes, int n_in,
                              void* d_out, int out_size) {
    const float* emb = (const float*)d_in[0];
    const float* w   = (const float*)d_in[1];
    const void*  gt  = (const void*)d_in[2];
    float*       out = (float*)d_out;

    int B = in_sizes[2];
    int D = in_sizes[0] / B;     // 512
    int C = in_sizes[1] / D;     // 100000
    int nCblk = (C + CTILE - 1) / CTILE;     // 1563
    int npart = nCblk * 2;

    static int smem_set = 0;
    if (!smem_set) {
        cudaFuncSetAttribute(k_gemm, cudaFuncAttributeMaxDynamicSharedMemorySize, SMEM_NEED);
        smem_set = 1;
    }

    k_probe<<<1, 256>>>(gt, B, C);
    k_norm_e<<<B, 256>>>(emb);
    k_wconv<<<WPAD / 8, 256>>>(w, C);
    k_phi<<<B, 256>>>(w, gt, C);
    dim3 grid(nCblk, B / STILE);
    k_gemm<<<grid, 256, SMEM_NEED>>>(C, npart);
    k_lse<<<B, 256>>>(npart);
    k_loss<<<1, 256>>>(out, B);
}